// round 15
// baseline (speedup 1.0000x reference)
#include <cuda_runtime.h>
#include <cuda_fp16.h>
#include <mma.h>
#include <math.h>

using namespace nvcuda;

#define NN 100000
#define DD 128
#define ND (NN * DD)
#define EMAX 1600000
#define NPART 782           // ceil(100000 / 128)

// ---------------- scratch (allocation-free: __device__ globals) ----------------
__device__ int    g_deg[2][NN];
__device__ float  g_norm[2][NN];
__device__ int    g_rowptr[2][NN + 1];
__device__ int    g_cursor[2][NN];
__device__ int    g_part[2][NPART];
__device__ int    g_col[2][EMAX];        // src ids grouped by dst
__device__ __half g_h16[2][3][ND];       // buf0 = fp16(feat0) persistent; buf1/2 ping-pong
__device__ float  g_fin[2][ND];          // fp32 final layer output per graph
__device__ __half g_w16[4][DD * DD];     // folded fp16 weights: beta*W + (1-beta)*I
__device__ double g_sum[2][DD];
__device__ double g_sumsq[2][DD];
__device__ float  g_mean[2][DD];
__device__ float  g_inv[2][DD];

// ---------------- init: zero deg + stats (both graphs, blockIdx.y = g) ----------
__global__ void k_init() {
    int g = blockIdx.y;
    int idx = blockIdx.x * blockDim.x + threadIdx.x;
    int stride = gridDim.x * blockDim.x;
    for (int i = idx; i < NN; i += stride) g_deg[g][i] = 0;
    if (idx < DD) { g_sum[g][idx] = 0.0; g_sumsq[g][idx] = 0.0; }
}

// ---------------- degree histogram (both graphs) ----------------
__global__ void k_count(const int* __restrict__ dst0, const int* __restrict__ dst1, int E) {
    int g = blockIdx.y;
    const int* dst = g ? dst1 : dst0;
    int i = blockIdx.x * blockDim.x + threadIdx.x;
    if (i < E) atomicAdd(&g_deg[g][dst[i]], 1);
}

// ---------------- convert input features to fp16 (both graphs) -> buf0 ----------
__global__ void k_tofp16(const float* __restrict__ f0, const float* __restrict__ f1) {
    int g = blockIdx.y;
    const float4* src = reinterpret_cast<const float4*>(g ? f1 : f0);
    uint2* dst = reinterpret_cast<uint2*>(g_h16[g][0]);
    int idx = blockIdx.x * blockDim.x + threadIdx.x;
    int stride = gridDim.x * blockDim.x;
    for (int i = idx; i < ND / 4; i += stride) {
        float4 v = src[i];
        __half2 lo = __floats2half2_rn(v.x, v.y);
        __half2 hi = __floats2half2_rn(v.z, v.w);
        uint2 o;
        o.x = *reinterpret_cast<unsigned*>(&lo);
        o.y = *reinterpret_cast<unsigned*>(&hi);
        dst[i] = o;
    }
}

// ---------------- fold weights: W'[l] = beta_l * W[l] + (1-beta_l) * I, fp16 -----
__global__ void k_wfold(const float* __restrict__ W) {
    int l = blockIdx.y;
    float beta = logf(1.0f / (float)(l + 1) + 1.0f);
    int idx = blockIdx.x * blockDim.x + threadIdx.x;   // 0 .. 16383
    int k = idx >> 7, n = idx & 127;
    float v = beta * W[(size_t)l * DD * DD + idx];
    if (k == n) v += 1.0f - beta;
    g_w16[l][idx] = __float2half_rn(v);
}

// ---------------- scan stage 1: per-block (128 elems) partial sums ----------------
__global__ void __launch_bounds__(128) k_scan1() {
    int g = blockIdx.y;
    __shared__ int wsum[4];
    int t = threadIdx.x;
    int i = blockIdx.x * 128 + t;
    int v = (i < NN) ? g_deg[g][i] : 0;
    int x = v;
    for (int o = 16; o > 0; o >>= 1) x += __shfl_down_sync(0xffffffffu, x, o);
    if ((t & 31) == 0) wsum[t >> 5] = x;
    __syncthreads();
    if (t == 0) g_part[g][blockIdx.x] = wsum[0] + wsum[1] + wsum[2] + wsum[3];
}

// ---------------- scan stage 2: exclusive scan of NPART partials (1 block/graph) -
__global__ void __launch_bounds__(1024) k_scan2() {
    int g = blockIdx.y;
    __shared__ int sm[1024];
    int t = threadIdx.x;
    sm[t] = (t < NPART) ? g_part[g][t] : 0;
    __syncthreads();
    for (int off = 1; off < 1024; off <<= 1) {
        int v = sm[t];
        int add = (t >= off) ? sm[t - off] : 0;
        __syncthreads();
        sm[t] = v + add;
        __syncthreads();
    }
    if (t < NPART) g_part[g][t] = (t == 0) ? 0 : sm[t - 1];
    if (t == 0) g_rowptr[g][NN] = sm[NPART - 1];
}

// ---------------- scan stage 3: block-local scan + offset; also compute norm -----
__global__ void __launch_bounds__(128) k_scan3() {
    int g = blockIdx.y;
    __shared__ int wsum[4], woff[4];
    int t = threadIdx.x;
    int lane = t & 31, wid = t >> 5;
    int i = blockIdx.x * 128 + t;
    int v = (i < NN) ? g_deg[g][i] : 0;
    int x = v;
    for (int o = 1; o < 32; o <<= 1) {
        int y = __shfl_up_sync(0xffffffffu, x, o);
        if (lane >= o) x += y;
    }
    if (lane == 31) wsum[wid] = x;
    __syncthreads();
    if (t == 0) {
        int r = 0;
        for (int k = 0; k < 4; k++) { woff[k] = r; r += wsum[k]; }
    }
    __syncthreads();
    int excl = x - v + woff[wid] + g_part[g][blockIdx.x];
    if (i < NN) {
        g_rowptr[g][i] = excl;
        g_cursor[g][i] = excl;
        g_norm[g][i] = rsqrtf(fmaxf((float)v, 1.f));
    }
}

// ---------------- CSR fill: col grouped by dst (both graphs) ----------------
__global__ void k_fill(const int* __restrict__ src0, const int* __restrict__ dst0,
                       const int* __restrict__ src1, const int* __restrict__ dst1, int E) {
    int g = blockIdx.y;
    const int* src = g ? src1 : src0;
    const int* dst = g ? dst1 : dst0;
    int i = blockIdx.x * blockDim.x + threadIdx.x;
    if (i < E) {
        int pos = atomicAdd(&g_cursor[g][dst[i]], 1);
        g_col[g][pos] = src[i];
    }
}

// ---------------- gather helpers ----------------
__device__ __forceinline__ void acc_edge(float4& acc, const uint2* feat8, int s,
                                         float c, int lane) {
    uint2 u = feat8[(size_t)s * 32 + lane];
    float2 a = __half22float2(*reinterpret_cast<__half2*>(&u.x));
    float2 b = __half22float2(*reinterpret_cast<__half2*>(&u.y));
    acc.x += a.x * c;
    acc.y += a.y * c;
    acc.z += b.x * c;
    acc.w += b.y * c;
}

// ---------------- fused gather(fp16) + wmma GEMM layer, ONE graph per launch -----
// h = 0.9*agg*norm + 0.1*feat0(fp16); out = relu(h @ W' + bias); W' identity-folded.
// Layer 3 additionally accumulates column stats.
__global__ void __launch_bounds__(256) k_layer(int g,
                                               const __half* __restrict__ s16,
                                               __half* __restrict__ dsth,
                                               float* __restrict__ dstf,
                                               const __half* __restrict__ f016p,
                                               const __half* __restrict__ Wf,
                                               const float* __restrict__ bias,
                                               int is_last) {
    __shared__ __align__(16) unsigned char smem_raw[64 * DD * 4];  // 32 KB
    __half* hs16 = reinterpret_cast<__half*>(smem_raw);            // [64][128] fp16
    float* outs = reinterpret_cast<float*>(smem_raw);              // [64][128] fp32

    const uint2* feat8 = reinterpret_cast<const uint2*>(s16);
    const uint2* f016 = reinterpret_cast<const uint2*>(f016p);

    int row0 = blockIdx.x * 64;
    int tid = threadIdx.x;
    int w = tid >> 5, lane = tid & 31;

    const int* __restrict__ rp = g_rowptr[g];
    const int* __restrict__ col = g_col[g];
    const float* __restrict__ nrm = g_norm[g];

    // ---- gather phase: warp w handles rows [8w, 8w+8) as 4 interleaved pairs ----
    for (int pr = 0; pr < 4; pr++) {
        int rA = w * 8 + pr * 2;
        int rB = rA + 1;
        int nA = row0 + rA, nB = row0 + rB;
        float4 aA = make_float4(0.f, 0.f, 0.f, 0.f);
        float4 aB = make_float4(0.f, 0.f, 0.f, 0.f);
        int eA = 0, endA = 0, eB = 0, endB = 0;
        if (nA < NN) { eA = __ldg(&rp[nA]); endA = __ldg(&rp[nA + 1]); }
        if (nB < NN) { eB = __ldg(&rp[nB]); endB = __ldg(&rp[nB + 1]); }

        while (eA + 1 < endA && eB + 1 < endB) {
            int sA0 = __ldg(&col[eA]);
            int sA1 = __ldg(&col[eA + 1]);
            int sB0 = __ldg(&col[eB]);
            int sB1 = __ldg(&col[eB + 1]);
            float cA0 = __ldg(&nrm[sA0]);
            float cA1 = __ldg(&nrm[sA1]);
            float cB0 = __ldg(&nrm[sB0]);
            float cB1 = __ldg(&nrm[sB1]);
            acc_edge(aA, feat8, sA0, cA0, lane);
            acc_edge(aA, feat8, sA1, cA1, lane);
            acc_edge(aB, feat8, sB0, cB0, lane);
            acc_edge(aB, feat8, sB1, cB1, lane);
            eA += 2; eB += 2;
        }
        for (; eA + 1 < endA; eA += 2) {
            int s0 = __ldg(&col[eA]);
            int s1 = __ldg(&col[eA + 1]);
            float c0 = __ldg(&nrm[s0]);
            float c1 = __ldg(&nrm[s1]);
            acc_edge(aA, feat8, s0, c0, lane);
            acc_edge(aA, feat8, s1, c1, lane);
        }
        if (eA < endA) {
            int s0 = __ldg(&col[eA]);
            acc_edge(aA, feat8, s0, __ldg(&nrm[s0]), lane);
        }
        for (; eB + 1 < endB; eB += 2) {
            int s0 = __ldg(&col[eB]);
            int s1 = __ldg(&col[eB + 1]);
            float c0 = __ldg(&nrm[s0]);
            float c1 = __ldg(&nrm[s1]);
            acc_edge(aB, feat8, s0, c0, lane);
            acc_edge(aB, feat8, s1, c1, lane);
        }
        if (eB < endB) {
            int s0 = __ldg(&col[eB]);
            acc_edge(aB, feat8, s0, __ldg(&nrm[s0]), lane);
        }

        // residual (fp16 feat0) + store h as fp16
        if (nA < NN) {
            float nr = nrm[nA];
            uint2 u = f016[(size_t)nA * 32 + lane];
            float2 fa = __half22float2(*reinterpret_cast<__half2*>(&u.x));
            float2 fb = __half22float2(*reinterpret_cast<__half2*>(&u.y));
            aA.x = 0.9f * aA.x * nr + 0.1f * fa.x;
            aA.y = 0.9f * aA.y * nr + 0.1f * fa.y;
            aA.z = 0.9f * aA.z * nr + 0.1f * fb.x;
            aA.w = 0.9f * aA.w * nr + 0.1f * fb.y;
        }
        if (nB < NN) {
            float nr = nrm[nB];
            uint2 u = f016[(size_t)nB * 32 + lane];
            float2 fa = __half22float2(*reinterpret_cast<__half2*>(&u.x));
            float2 fb = __half22float2(*reinterpret_cast<__half2*>(&u.y));
            aB.x = 0.9f * aB.x * nr + 0.1f * fa.x;
            aB.y = 0.9f * aB.y * nr + 0.1f * fa.y;
            aB.z = 0.9f * aB.z * nr + 0.1f * fb.x;
            aB.w = 0.9f * aB.w * nr + 0.1f * fb.y;
        }
        {
            __half2 lo = __floats2half2_rn(aA.x, aA.y);
            __half2 hi = __floats2half2_rn(aA.z, aA.w);
            uint2 o;
            o.x = *reinterpret_cast<unsigned*>(&lo);
            o.y = *reinterpret_cast<unsigned*>(&hi);
            reinterpret_cast<uint2*>(&hs16[rA * DD])[lane] = o;
            lo = __floats2half2_rn(aB.x, aB.y);
            hi = __floats2half2_rn(aB.z, aB.w);
            o.x = *reinterpret_cast<unsigned*>(&lo);
            o.y = *reinterpret_cast<unsigned*>(&hi);
            reinterpret_cast<uint2*>(&hs16[rB * DD])[lane] = o;
        }
    }
    __syncthreads();

    // ---- wmma phase: warp w -> row tile (w>>1)*16, col half (w&1)*64 ----
    {
        int rt = w >> 1;
        int ch = w & 1;
        wmma::fragment<wmma::accumulator, 16, 16, 16, float> fc[4];
#pragma unroll
        for (int ct = 0; ct < 4; ct++) wmma::fill_fragment(fc[ct], 0.f);

#pragma unroll
        for (int k0 = 0; k0 < 8; k0++) {
            wmma::fragment<wmma::matrix_a, 16, 16, 16, __half, wmma::row_major> fa;
            wmma::load_matrix_sync(fa, &hs16[(rt * 16) * DD + k0 * 16], DD);
#pragma unroll
            for (int ct = 0; ct < 4; ct++) {
                wmma::fragment<wmma::matrix_b, 16, 16, 16, __half, wmma::row_major> fb;
                wmma::load_matrix_sync(fb, &Wf[(k0 * 16) * DD + ch * 64 + ct * 16], DD);
                wmma::mma_sync(fc[ct], fa, fb, fc[ct]);
            }
        }
        __syncthreads();   // all frag_a loads done; safe to overwrite smem as fp32
#pragma unroll
        for (int ct = 0; ct < 4; ct++)
            wmma::store_matrix_sync(&outs[(rt * 16) * DD + ch * 64 + ct * 16], fc[ct],
                                    DD, wmma::mem_row_major);
    }
    __syncthreads();

    // ---- epilogue: o = relu(outs + bias); column pairs (2*lane + 64j) ----
    float csum[4] = {0.f, 0.f, 0.f, 0.f};
    float csq[4] = {0.f, 0.f, 0.f, 0.f};
#pragma unroll
    for (int r8 = 0; r8 < 8; r8++) {
        int r = w * 8 + r8;
        int n = row0 + r;
        if (n >= NN) continue;
#pragma unroll
        for (int j = 0; j < 2; j++) {
            int c = 2 * lane + 64 * j;
            float o0 = outs[r * DD + c] + __ldg(&bias[c]);
            float o1 = outs[r * DD + c + 1] + __ldg(&bias[c + 1]);
            o0 = fmaxf(o0, 0.f);
            o1 = fmaxf(o1, 0.f);
            if (is_last) {
                dstf[(size_t)n * DD + c] = o0;
                dstf[(size_t)n * DD + c + 1] = o1;
                csum[2 * j] += o0;  csq[2 * j] += o0 * o0;
                csum[2 * j + 1] += o1;  csq[2 * j + 1] += o1 * o1;
            } else {
                __half2 h2 = __floats2half2_rn(o0, o1);
                *reinterpret_cast<__half2*>(&dsth[(size_t)n * DD + c]) = h2;
            }
        }
    }

    if (is_last) {
        __syncthreads();
        float* red = outs; // reuse as [16][128]: rows 0-7 sum, 8-15 sumsq
#pragma unroll
        for (int j = 0; j < 2; j++) {
            red[w * DD + 2 * lane + 64 * j] = csum[2 * j];
            red[w * DD + 2 * lane + 64 * j + 1] = csum[2 * j + 1];
            red[(8 + w) * DD + 2 * lane + 64 * j] = csq[2 * j];
            red[(8 + w) * DD + 2 * lane + 64 * j + 1] = csq[2 * j + 1];
        }
        __syncthreads();
        int c = tid & 127;
        int which = tid >> 7;
        float tot = 0.f;
#pragma unroll
        for (int w2 = 0; w2 < 8; w2++) tot += red[(which * 8 + w2) * DD + c];
        if (which == 0) atomicAdd(&g_sum[g][c], (double)tot);
        else            atomicAdd(&g_sumsq[g][c], (double)tot);
    }
}

__global__ void k_finalize() {
    int g = blockIdx.y;
    int c = threadIdx.x;
    if (c < DD) {
        double mean = g_sum[g][c] / (double)NN;
        double var = (g_sumsq[g][c] - (double)NN * mean * mean) / (double)(NN - 1);
        if (var < 0.0) var = 0.0;
        float sd = (float)sqrt(var);
        g_mean[g][c] = (float)mean;
        g_inv[g][c] = 1.f / fmaxf(sd, 1e-12f);
    }
}

__global__ void k_write(const float* __restrict__ feat0, const float* __restrict__ feat1,
                        float* __restrict__ out) {
    int g = blockIdx.y;
    const float4* feat = reinterpret_cast<const float4*>(g ? feat1 : feat0);
    float4* o = reinterpret_cast<float4*>(out + (size_t)g * ND);
    int idx = blockIdx.x * blockDim.x + threadIdx.x;
    int stride = gridDim.x * blockDim.x;
    for (int i = idx; i < ND / 4; i += stride) {
        int c = (i * 4) & 127;
        float4 v = feat[i];
        v.x = (v.x - g_mean[g][c]) * g_inv[g][c];
        v.y = (v.y - g_mean[g][c + 1]) * g_inv[g][c + 1];
        v.z = (v.z - g_mean[g][c + 2]) * g_inv[g][c + 2];
        v.w = (v.w - g_mean[g][c + 3]) * g_inv[g][c + 3];
        o[i] = v;
    }
}

// ---------------- launch (single stream — capture-safe) ----------------
extern "C" void kernel_launch(void* const* d_in, const int* in_sizes, int n_in,
                              void* d_out, int out_size) {
    const float* feat0 = (const float*)d_in[0];
    const float* feat1 = (const float*)d_in[1];
    const int* src0 = (const int*)d_in[2];
    const int* dst0 = (const int*)d_in[3];
    const int* src1 = (const int*)d_in[4];
    const int* dst1 = (const int*)d_in[5];
    const float* weights = (const float*)d_in[6];
    const float* biases = (const float*)d_in[7];
    int E = in_sizes[2];
    float* out = (float*)d_out;

    static __half* h16_addr[2][3] = {{nullptr, nullptr, nullptr},
                                     {nullptr, nullptr, nullptr}};
    static float* fin_addr[2] = {nullptr, nullptr};
    static __half* w16_addr = nullptr;
    if (!h16_addr[0][0]) {
        void* p = nullptr;
        cudaGetSymbolAddress(&p, g_h16);
        __half* hbase = (__half*)p;
        for (int g = 0; g < 2; g++)
            for (int b = 0; b < 3; b++)
                h16_addr[g][b] = hbase + ((size_t)g * 3 + b) * (size_t)ND;
        cudaGetSymbolAddress(&p, g_fin);
        float* fbase = (float*)p;
        for (int g = 0; g < 2; g++) fin_addr[g] = fbase + (size_t)g * ND;
        cudaGetSymbolAddress(&p, g_w16);
        w16_addr = (__half*)p;
    }

    int eb = (E + 255) / 256;
    int layer_blocks = (NN + 63) / 64;

    k_init<<<dim3(256, 2), 256>>>();
    k_count<<<dim3(eb, 2), 256>>>(dst0, dst1, E);
    k_tofp16<<<dim3(1024, 2), 256>>>(feat0, feat1);
    k_wfold<<<dim3(64, 4), 256>>>(weights);
    k_scan1<<<dim3(NPART, 2), 128>>>();
    k_scan2<<<dim3(1, 2), 1024>>>();
    k_scan3<<<dim3(NPART, 2), 128>>>();
    k_fill<<<dim3(eb, 2), 256>>>(src0, dst0, src1, dst1, E);

    // buf0 = fp16(feat0), persistent (residual source).
    // One graph per layer launch: per-graph working set (~83 MB) fits L2, and
    // a graph's 4 layers run back-to-back so ping-pong buffers stay resident.
    const int sbuf[4] = {0, 1, 2, 1};
    const int dbuf[4] = {1, 2, 1, 0 /*unused on last*/};
    for (int g = 0; g < 2; g++) {
        for (int l = 0; l < 4; l++) {
            int is_last = (l == 3) ? 1 : 0;
            k_layer<<<layer_blocks, 256>>>(g,
                                           h16_addr[g][sbuf[l]],
                                           h16_addr[g][dbuf[l]],
                                           fin_addr[g],
                                           h16_addr[g][0],
                                           w16_addr + (size_t)l * DD * DD,
                                           biases + (size_t)l * DD, is_last);
        }
    }

    k_finalize<<<dim3(1, 2), DD>>>();
    k_write<<<dim3(1024, 2), 256>>>(fin_addr[0], fin_addr[1], out);
}

// round 17
// speedup vs baseline: 1.0805x; 1.0805x over previous
#include <cuda_runtime.h>
#include <cuda_fp16.h>
#include <mma.h>
#include <math.h>

using namespace nvcuda;

#define NN 100000
#define DD 128
#define ND (NN * DD)
#define EMAX 1600000
#define NPART 782           // ceil(100000 / 128)

// ---------------- scratch (allocation-free: __device__ globals) ----------------
__device__ int    g_deg[2][NN];
__device__ float  g_norm[2][NN];
__device__ int    g_rowptr[2][NN + 1];
__device__ int    g_cursor[2][NN];
__device__ int    g_part[2][NPART];
__device__ int    g_col[2][EMAX];        // src ids grouped by dst
__device__ __half g_h16[2][3][ND];       // buf0 = fp16(feat0); buf1/2 = norm-scaled ping-pong
__device__ float  g_fin[2][ND];          // fp32 final layer output per graph
__device__ __half g_w16[4][DD * DD];     // folded fp16 weights: beta*W + (1-beta)*I
__device__ double g_sum[2][DD];
__device__ double g_sumsq[2][DD];
__device__ float  g_mean[2][DD];
__device__ float  g_inv[2][DD];

// ---------------- init: zero deg + stats (both graphs, blockIdx.y = g) ----------
__global__ void k_init() {
    int g = blockIdx.y;
    int idx = blockIdx.x * blockDim.x + threadIdx.x;
    int stride = gridDim.x * blockDim.x;
    for (int i = idx; i < NN; i += stride) g_deg[g][i] = 0;
    if (idx < DD) { g_sum[g][idx] = 0.0; g_sumsq[g][idx] = 0.0; }
}

// ---------------- degree histogram (both graphs) ----------------
__global__ void k_count(const int* __restrict__ dst0, const int* __restrict__ dst1, int E) {
    int g = blockIdx.y;
    const int* dst = g ? dst1 : dst0;
    int i = blockIdx.x * blockDim.x + threadIdx.x;
    if (i < E) atomicAdd(&g_deg[g][dst[i]], 1);
}

// ---------------- convert input feats to fp16: buf0 unscaled, buf1 = feat*norm ---
// must run AFTER k_scan3 (needs g_norm).
__global__ void k_tofp16(const float* __restrict__ f0, const float* __restrict__ f1) {
    int g = blockIdx.y;
    const float4* src = reinterpret_cast<const float4*>(g ? f1 : f0);
    uint2* dst0 = reinterpret_cast<uint2*>(g_h16[g][0]);
    uint2* dst1 = reinterpret_cast<uint2*>(g_h16[g][1]);
    int idx = blockIdx.x * blockDim.x + threadIdx.x;
    int stride = gridDim.x * blockDim.x;
    for (int i = idx; i < ND / 4; i += stride) {
        float4 v = src[i];
        float nr = g_norm[g][i >> 5];          // row = i*4/128
        __half2 lo = __floats2half2_rn(v.x, v.y);
        __half2 hi = __floats2half2_rn(v.z, v.w);
        uint2 o;
        o.x = *reinterpret_cast<unsigned*>(&lo);
        o.y = *reinterpret_cast<unsigned*>(&hi);
        dst0[i] = o;
        lo = __floats2half2_rn(v.x * nr, v.y * nr);
        hi = __floats2half2_rn(v.z * nr, v.w * nr);
        o.x = *reinterpret_cast<unsigned*>(&lo);
        o.y = *reinterpret_cast<unsigned*>(&hi);
        dst1[i] = o;
    }
}

// ---------------- fold weights: W'[l] = beta_l * W[l] + (1-beta_l) * I, fp16 -----
__global__ void k_wfold(const float* __restrict__ W) {
    int l = blockIdx.y;
    float beta = logf(1.0f / (float)(l + 1) + 1.0f);
    int idx = blockIdx.x * blockDim.x + threadIdx.x;   // 0 .. 16383
    int k = idx >> 7, n = idx & 127;
    float v = beta * W[(size_t)l * DD * DD + idx];
    if (k == n) v += 1.0f - beta;
    g_w16[l][idx] = __float2half_rn(v);
}

// ---------------- scan stage 1: per-block (128 elems) partial sums ----------------
__global__ void __launch_bounds__(128) k_scan1() {
    int g = blockIdx.y;
    __shared__ int wsum[4];
    int t = threadIdx.x;
    int i = blockIdx.x * 128 + t;
    int v = (i < NN) ? g_deg[g][i] : 0;
    int x = v;
    for (int o = 16; o > 0; o >>= 1) x += __shfl_down_sync(0xffffffffu, x, o);
    if ((t & 31) == 0) wsum[t >> 5] = x;
    __syncthreads();
    if (t == 0) g_part[g][blockIdx.x] = wsum[0] + wsum[1] + wsum[2] + wsum[3];
}

// ---------------- scan stage 2: exclusive scan of NPART partials (1 block/graph) -
__global__ void __launch_bounds__(1024) k_scan2() {
    int g = blockIdx.y;
    __shared__ int sm[1024];
    int t = threadIdx.x;
    sm[t] = (t < NPART) ? g_part[g][t] : 0;
    __syncthreads();
    for (int off = 1; off < 1024; off <<= 1) {
        int v = sm[t];
        int add = (t >= off) ? sm[t - off] : 0;
        __syncthreads();
        sm[t] = v + add;
        __syncthreads();
    }
    if (t < NPART) g_part[g][t] = (t == 0) ? 0 : sm[t - 1];
    if (t == 0) g_rowptr[g][NN] = sm[NPART - 1];
}

// ---------------- scan stage 3: block-local scan + offset; also compute norm -----
__global__ void __launch_bounds__(128) k_scan3() {
    int g = blockIdx.y;
    __shared__ int wsum[4], woff[4];
    int t = threadIdx.x;
    int lane = t & 31, wid = t >> 5;
    int i = blockIdx.x * 128 + t;
    int v = (i < NN) ? g_deg[g][i] : 0;
    int x = v;
    for (int o = 1; o < 32; o <<= 1) {
        int y = __shfl_up_sync(0xffffffffu, x, o);
        if (lane >= o) x += y;
    }
    if (lane == 31) wsum[wid] = x;
    __syncthreads();
    if (t == 0) {
        int r = 0;
        for (int k = 0; k < 4; k++) { woff[k] = r; r += wsum[k]; }
    }
    __syncthreads();
    int excl = x - v + woff[wid] + g_part[g][blockIdx.x];
    if (i < NN) {
        g_rowptr[g][i] = excl;
        g_cursor[g][i] = excl;
        g_norm[g][i] = rsqrtf(fmaxf((float)v, 1.f));
    }
}

// ---------------- CSR fill: col grouped by dst (both graphs) ----------------
__global__ void k_fill(const int* __restrict__ src0, const int* __restrict__ dst0,
                       const int* __restrict__ src1, const int* __restrict__ dst1, int E) {
    int g = blockIdx.y;
    const int* src = g ? src1 : src0;
    const int* dst = g ? dst1 : dst0;
    int i = blockIdx.x * blockDim.x + threadIdx.x;
    if (i < E) {
        int pos = atomicAdd(&g_cursor[g][dst[i]], 1);
        g_col[g][pos] = src[i];
    }
}

// ---------------- gather helper: acc += x̃[s] (pre-scaled, no norm mult) ----------
__device__ __forceinline__ void acc_edge(float4& acc, const uint2* feat8, int s, int lane) {
    uint2 u = feat8[(size_t)s * 32 + lane];
    float2 a = __half22float2(*reinterpret_cast<__half2*>(&u.x));
    float2 b = __half22float2(*reinterpret_cast<__half2*>(&u.y));
    acc.x += a.x;
    acc.y += a.y;
    acc.z += b.x;
    acc.w += b.y;
}

// ---------------- fused gather(fp16, pre-scaled) + wmma GEMM, both graphs --------
// agg = Σ x̃[s];  h = 0.9*agg*norm[n] + 0.1*feat0;  o = relu(h @ W' + bias).
// Layers 0-2 store fp16(o * norm[n]) for the next gather; layer 3 stores fp32 o + stats.
__global__ void __launch_bounds__(256) k_layer(const __half* __restrict__ s16_0,
                                               const __half* __restrict__ s16_1,
                                               __half* __restrict__ dh0,
                                               __half* __restrict__ dh1,
                                               float* __restrict__ df0,
                                               float* __restrict__ df1,
                                               const __half* __restrict__ f016_0,
                                               const __half* __restrict__ f016_1,
                                               const __half* __restrict__ Wf,
                                               const float* __restrict__ bias,
                                               int is_last) {
    __shared__ __align__(16) unsigned char smem_raw[64 * DD * 4];  // 32 KB
    __half* hs16 = reinterpret_cast<__half*>(smem_raw);            // [64][128] fp16
    float* outs = reinterpret_cast<float*>(smem_raw);              // [64][128] fp32

    int g = blockIdx.y;
    const uint2* feat8 = reinterpret_cast<const uint2*>(g ? s16_1 : s16_0);
    const uint2* f016 = reinterpret_cast<const uint2*>(g ? f016_1 : f016_0);
    __half* dsth = g ? dh1 : dh0;
    float* dstf = g ? df1 : df0;

    int row0 = blockIdx.x * 64;
    int tid = threadIdx.x;
    int w = tid >> 5, lane = tid & 31;

    const int* __restrict__ rp = g_rowptr[g];
    const int* __restrict__ col = g_col[g];
    const float* __restrict__ nrm = g_norm[g];

    // ---- gather phase: warp w handles rows [8w, 8w+8) as 4 interleaved pairs ----
    for (int pr = 0; pr < 4; pr++) {
        int rA = w * 8 + pr * 2;
        int rB = rA + 1;
        int nA = row0 + rA, nB = row0 + rB;
        float4 aA = make_float4(0.f, 0.f, 0.f, 0.f);
        float4 aB = make_float4(0.f, 0.f, 0.f, 0.f);
        int eA = 0, endA = 0, eB = 0, endB = 0;
        if (nA < NN) { eA = __ldg(&rp[nA]); endA = __ldg(&rp[nA + 1]); }
        if (nB < NN) { eB = __ldg(&rp[nB]); endB = __ldg(&rp[nB + 1]); }

        while (eA + 1 < endA && eB + 1 < endB) {
            int sA0 = __ldg(&col[eA]);
            int sA1 = __ldg(&col[eA + 1]);
            int sB0 = __ldg(&col[eB]);
            int sB1 = __ldg(&col[eB + 1]);
            acc_edge(aA, feat8, sA0, lane);
            acc_edge(aA, feat8, sA1, lane);
            acc_edge(aB, feat8, sB0, lane);
            acc_edge(aB, feat8, sB1, lane);
            eA += 2; eB += 2;
        }
        for (; eA + 1 < endA; eA += 2) {
            int s0 = __ldg(&col[eA]);
            int s1 = __ldg(&col[eA + 1]);
            acc_edge(aA, feat8, s0, lane);
            acc_edge(aA, feat8, s1, lane);
        }
        if (eA < endA) acc_edge(aA, feat8, __ldg(&col[eA]), lane);
        for (; eB + 1 < endB; eB += 2) {
            int s0 = __ldg(&col[eB]);
            int s1 = __ldg(&col[eB + 1]);
            acc_edge(aB, feat8, s0, lane);
            acc_edge(aB, feat8, s1, lane);
        }
        if (eB < endB) acc_edge(aB, feat8, __ldg(&col[eB]), lane);

        // residual (fp16 feat0) + store h as fp16
        if (nA < NN) {
            float nr = 0.9f * nrm[nA];
            uint2 u = f016[(size_t)nA * 32 + lane];
            float2 fa = __half22float2(*reinterpret_cast<__half2*>(&u.x));
            float2 fb = __half22float2(*reinterpret_cast<__half2*>(&u.y));
            aA.x = aA.x * nr + 0.1f * fa.x;
            aA.y = aA.y * nr + 0.1f * fa.y;
            aA.z = aA.z * nr + 0.1f * fb.x;
            aA.w = aA.w * nr + 0.1f * fb.y;
        }
        if (nB < NN) {
            float nr = 0.9f * nrm[nB];
            uint2 u = f016[(size_t)nB * 32 + lane];
            float2 fa = __half22float2(*reinterpret_cast<__half2*>(&u.x));
            float2 fb = __half22float2(*reinterpret_cast<__half2*>(&u.y));
            aB.x = aB.x * nr + 0.1f * fa.x;
            aB.y = aB.y * nr + 0.1f * fa.y;
            aB.z = aB.z * nr + 0.1f * fb.x;
            aB.w = aB.w * nr + 0.1f * fb.y;
        }
        {
            __half2 lo = __floats2half2_rn(aA.x, aA.y);
            __half2 hi = __floats2half2_rn(aA.z, aA.w);
            uint2 o;
            o.x = *reinterpret_cast<unsigned*>(&lo);
            o.y = *reinterpret_cast<unsigned*>(&hi);
            reinterpret_cast<uint2*>(&hs16[rA * DD])[lane] = o;
            lo = __floats2half2_rn(aB.x, aB.y);
            hi = __floats2half2_rn(aB.z, aB.w);
            o.x = *reinterpret_cast<unsigned*>(&lo);
            o.y = *reinterpret_cast<unsigned*>(&hi);
            reinterpret_cast<uint2*>(&hs16[rB * DD])[lane] = o;
        }
    }
    __syncthreads();

    // ---- wmma phase: warp w -> row tile (w>>1)*16, col half (w&1)*64 ----
    {
        int rt = w >> 1;
        int ch = w & 1;
        wmma::fragment<wmma::accumulator, 16, 16, 16, float> fc[4];
#pragma unroll
        for (int ct = 0; ct < 4; ct++) wmma::fill_fragment(fc[ct], 0.f);

#pragma unroll
        for (int k0 = 0; k0 < 8; k0++) {
            wmma::fragment<wmma::matrix_a, 16, 16, 16, __half, wmma::row_major> fa;
            wmma::load_matrix_sync(fa, &hs16[(rt * 16) * DD + k0 * 16], DD);
#pragma unroll
            for (int ct = 0; ct < 4; ct++) {
                wmma::fragment<wmma::matrix_b, 16, 16, 16, __half, wmma::row_major> fb;
                wmma::load_matrix_sync(fb, &Wf[(k0 * 16) * DD + ch * 64 + ct * 16], DD);
                wmma::mma_sync(fc[ct], fa, fb, fc[ct]);
            }
        }
        __syncthreads();   // all frag_a loads done; safe to overwrite smem as fp32
#pragma unroll
        for (int ct = 0; ct < 4; ct++)
            wmma::store_matrix_sync(&outs[(rt * 16) * DD + ch * 64 + ct * 16], fc[ct],
                                    DD, wmma::mem_row_major);
    }
    __syncthreads();

    // ---- epilogue: o = relu(outs + bias); store o*norm (fp16) or o (fp32+stats) --
    float csum[4] = {0.f, 0.f, 0.f, 0.f};
    float csq[4] = {0.f, 0.f, 0.f, 0.f};
#pragma unroll
    for (int r8 = 0; r8 < 8; r8++) {
        int r = w * 8 + r8;
        int n = row0 + r;
        if (n >= NN) continue;
        float nr = nrm[n];
#pragma unroll
        for (int j = 0; j < 2; j++) {
            int c = 2 * lane + 64 * j;
            float o0 = outs[r * DD + c] + __ldg(&bias[c]);
            float o1 = outs[r * DD + c + 1] + __ldg(&bias[c + 1]);
            o0 = fmaxf(o0, 0.f);
            o1 = fmaxf(o1, 0.f);
            if (is_last) {
                dstf[(size_t)n * DD + c] = o0;
                dstf[(size_t)n * DD + c + 1] = o1;
                csum[2 * j] += o0;  csq[2 * j] += o0 * o0;
                csum[2 * j + 1] += o1;  csq[2 * j + 1] += o1 * o1;
            } else {
                __half2 h2 = __floats2half2_rn(o0 * nr, o1 * nr);
                *reinterpret_cast<__half2*>(&dsth[(size_t)n * DD + c]) = h2;
            }
        }
    }

    if (is_last) {
        __syncthreads();
        float* red = outs; // reuse as [16][128]: rows 0-7 sum, 8-15 sumsq
#pragma unroll
        for (int j = 0; j < 2; j++) {
            red[w * DD + 2 * lane + 64 * j] = csum[2 * j];
            red[w * DD + 2 * lane + 64 * j + 1] = csum[2 * j + 1];
            red[(8 + w) * DD + 2 * lane + 64 * j] = csq[2 * j];
            red[(8 + w) * DD + 2 * lane + 64 * j + 1] = csq[2 * j + 1];
        }
        __syncthreads();
        int c = tid & 127;
        int which = tid >> 7;
        float tot = 0.f;
#pragma unroll
        for (int w2 = 0; w2 < 8; w2++) tot += red[(which * 8 + w2) * DD + c];
        if (which == 0) atomicAdd(&g_sum[g][c], (double)tot);
        else            atomicAdd(&g_sumsq[g][c], (double)tot);
    }
}

__global__ void k_finalize() {
    int g = blockIdx.y;
    int c = threadIdx.x;
    if (c < DD) {
        double mean = g_sum[g][c] / (double)NN;
        double var = (g_sumsq[g][c] - (double)NN * mean * mean) / (double)(NN - 1);
        if (var < 0.0) var = 0.0;
        float sd = (float)sqrt(var);
        g_mean[g][c] = (float)mean;
        g_inv[g][c] = 1.f / fmaxf(sd, 1e-12f);
    }
}

__global__ void k_write(const float* __restrict__ feat0, const float* __restrict__ feat1,
                        float* __restrict__ out) {
    int g = blockIdx.y;
    const float4* feat = reinterpret_cast<const float4*>(g ? feat1 : feat0);
    float4* o = reinterpret_cast<float4*>(out + (size_t)g * ND);
    int idx = blockIdx.x * blockDim.x + threadIdx.x;
    int stride = gridDim.x * blockDim.x;
    for (int i = idx; i < ND / 4; i += stride) {
        int c = (i * 4) & 127;
        float4 v = feat[i];
        v.x = (v.x - g_mean[g][c]) * g_inv[g][c];
        v.y = (v.y - g_mean[g][c + 1]) * g_inv[g][c + 1];
        v.z = (v.z - g_mean[g][c + 2]) * g_inv[g][c + 2];
        v.w = (v.w - g_mean[g][c + 3]) * g_inv[g][c + 3];
        o[i] = v;
    }
}

// ---------------- launch (single stream — capture-safe) ----------------
extern "C" void kernel_launch(void* const* d_in, const int* in_sizes, int n_in,
                              void* d_out, int out_size) {
    const float* feat0 = (const float*)d_in[0];
    const float* feat1 = (const float*)d_in[1];
    const int* src0 = (const int*)d_in[2];
    const int* dst0 = (const int*)d_in[3];
    const int* src1 = (const int*)d_in[4];
    const int* dst1 = (const int*)d_in[5];
    const float* weights = (const float*)d_in[6];
    const float* biases = (const float*)d_in[7];
    int E = in_sizes[2];
    float* out = (float*)d_out;

    static __half* h16_addr[2][3] = {{nullptr, nullptr, nullptr},
                                     {nullptr, nullptr, nullptr}};
    static float* fin_addr[2] = {nullptr, nullptr};
    static __half* w16_addr = nullptr;
    if (!h16_addr[0][0]) {
        void* p = nullptr;
        cudaGetSymbolAddress(&p, g_h16);
        __half* hbase = (__half*)p;
        for (int g = 0; g < 2; g++)
            for (int b = 0; b < 3; b++)
                h16_addr[g][b] = hbase + ((size_t)g * 3 + b) * (size_t)ND;
        cudaGetSymbolAddress(&p, g_fin);
        float* fbase = (float*)p;
        for (int g = 0; g < 2; g++) fin_addr[g] = fbase + (size_t)g * ND;
        cudaGetSymbolAddress(&p, g_w16);
        w16_addr = (__half*)p;
    }

    int eb = (E + 255) / 256;
    int layer_blocks = (NN + 63) / 64;

    k_init<<<dim3(256, 2), 256>>>();
    k_count<<<dim3(eb, 2), 256>>>(dst0, dst1, E);
    k_scan1<<<dim3(NPART, 2), 128>>>();
    k_scan2<<<dim3(1, 2), 1024>>>();
    k_scan3<<<dim3(NPART, 2), 128>>>();
    k_tofp16<<<dim3(1024, 2), 256>>>(feat0, feat1);   // after scan3: needs norm
    k_wfold<<<dim3(64, 4), 256>>>(weights);
    k_fill<<<dim3(eb, 2), 256>>>(src0, dst0, src1, dst1, E);

    // buf0 = fp16(feat0) unscaled (residual); buf1 = fp16(feat0*norm) (layer-0 src).
    // layers ping-pong the norm-scaled buffers; layer 3 writes fp32 g_fin + stats.
    const int sbuf[4] = {1, 2, 1, 2};
    const int dbuf[4] = {2, 1, 2, 1 /*unused on last*/};
    for (int l = 0; l < 4; l++) {
        int is_last = (l == 3) ? 1 : 0;
        k_layer<<<dim3(layer_blocks, 2), 256>>>(h16_addr[0][sbuf[l]], h16_addr[1][sbuf[l]],
                                                h16_addr[0][dbuf[l]], h16_addr[1][dbuf[l]],
                                                fin_addr[0], fin_addr[1],
                                                h16_addr[0][0], h16_addr[1][0],
                                                w16_addr + (size_t)l * DD * DD,
                                                biases + (size_t)l * DD, is_last);
    }

    k_finalize<<<dim3(1, 2), DD>>>();
    k_write<<<dim3(1024, 2), 256>>>(fin_addr[0], fin_addr[1], out);
}